// round 15
// baseline (speedup 1.0000x reference)
#include <cuda_runtime.h>
#include <cuda_fp16.h>
#include <cstdint>

// ---------------------------------------------------------------------------
// FlashSVDLlamaBlock R15: fp16 2-pass split GEMM (A_hi·W_hi + A_hi·W_lo),
// double-buffered single-sync pipeline. tcgen05 unavailable (compute_103).
// Plus R6 proj2 + packed-f32x2 flash.
//   B=2, T=1024, D=2048, H=32, HK=8, DH=64, R=48, RO=RFF=1024, INTER=8192
// Scratch (61 MB, phase-liveness reuse):
//   H [0..4,194,303]: hbuf -> attn -> hbuf -> dr
//   B [4,194,304..8,912,895]: qkvr -> ar -> gr/ur
//   C [8,912,896..15,204,351]: wc -> qb/kb/vb -> gate|inner|part (256-tok chunks)
// ---------------------------------------------------------------------------

#define NTOK 2048
#define DMODEL 2048
#define NH 32
#define NHK 8
#define DHEAD 64
#define RNK 48
#define TSEQ 1024
#define NCHUNK 256

#define OFF_H 0u
#define OFF_B 4194304u
#define OFF_C 8912896u
#define SCRATCH_TOTAL 15204352u

__device__ float g_scratch[SCRATCH_TOTAL];

typedef unsigned long long ull;

// ---- packed f32x2 helpers (flash attention) --------------------------------
__device__ __forceinline__ ull pk2(float v) {
    ull r; asm("mov.b64 %0, {%1, %1};" : "=l"(r) : "f"(v)); return r;
}
__device__ __forceinline__ void fma2(ull& c, ull a, ull b) {
    asm("fma.rn.f32x2 %0, %1, %2, %0;" : "+l"(c) : "l"(a), "l"(b));
}
__device__ __forceinline__ void mul2(ull& c, ull a) {
    asm("mul.rn.f32x2 %0, %0, %1;" : "+l"(c) : "l"(a));
}
__device__ __forceinline__ float2 upk2(ull v) {
    float2 r; asm("mov.b64 {%0, %1}, %2;" : "=f"(r.x), "=f"(r.y) : "l"(v)); return r;
}

// ---- tensor-core helpers (base ISA, sm_80+) --------------------------------
__device__ __forceinline__ uint32_t smem_to_u32(const void* p) {
    uint32_t a;
    asm("{ .reg .u64 t; cvta.to.shared.u64 t, %1; cvt.u32.u64 %0, t; }"
        : "=r"(a) : "l"(p));
    return a;
}
__device__ __forceinline__ void ldmx4(uint32_t* r, uint32_t addr) {
    asm volatile("ldmatrix.sync.aligned.m8n8.x4.shared.b16 {%0,%1,%2,%3}, [%4];"
                 : "=r"(r[0]), "=r"(r[1]), "=r"(r[2]), "=r"(r[3]) : "r"(addr));
}
__device__ __forceinline__ void ldmx2(uint32_t* r, uint32_t addr) {
    asm volatile("ldmatrix.sync.aligned.m8n8.x2.shared.b16 {%0,%1}, [%2];"
                 : "=r"(r[0]), "=r"(r[1]) : "r"(addr));
}
__device__ __forceinline__ void mma_fp16(float* c, const uint32_t* a,
                                         const uint32_t* b) {
    asm volatile(
        "mma.sync.aligned.m16n8k16.row.col.f32.f16.f16.f32 "
        "{%0,%1,%2,%3}, {%4,%5,%6,%7}, {%8,%9}, {%0,%1,%2,%3};"
        : "+f"(c[0]), "+f"(c[1]), "+f"(c[2]), "+f"(c[3])
        : "r"(a[0]), "r"(a[1]), "r"(a[2]), "r"(a[3]), "r"(b[0]), "r"(b[1]));
}
__device__ __forceinline__ uint32_t h2pack(float x, float y) {
    __half2 h = __float22half2_rn(make_float2(x, y));
    return *(uint32_t*)&h;
}

// ---------------------------------------------------------------------------
// mmfp16: C[n,m] = sum_k A[n,k]*W[m,k], tensor cores, fp16 2-pass split:
//   C ≈ A_hi·W_hi + A_hi·W_lo   (dropped A_lo·W ≈ 3e-4 rel)
//   MODE 0: C = d;  1: C = d + RG[n,m];  2: C += d;  3: C = silu(RG[n,m]) * d
// Tile 128(tok) x 128(feat), 8 warps (2x4), warp tile 64x32, BK=32.
// 2-stage dynamic smem (61,440 B), one __syncthreads per chunk.
// Smem rows stride 80 B (bank-conflict-free LDSM, no swizzle needed).
// Split-K via blockIdx.z (range Kt, out rows offset z*gridDim.y*128, MODE 0).
// ---------------------------------------------------------------------------
#define ST_AHI 0
#define ST_WHI 10240
#define ST_WLO 20480
#define ST_STRIDE 30720
#define MM_SMEM 61440

template <int MODE>
__global__ void __launch_bounds__(256, 2) mmfp16(const float* __restrict__ A,
                                                 const float* __restrict__ W,
                                                 const float* __restrict__ RG,
                                                 float* __restrict__ C,
                                                 int M, int K, int Kt) {
    extern __shared__ __align__(16) char sm[];
    int tid = threadIdx.x;
    int wid = tid >> 5, lane = tid & 31;
    int m0 = blockIdx.x * 128, n0 = blockIdx.y * 128;
    size_t koff = (size_t)blockIdx.z * Kt;
    const float* Ap = A + (size_t)n0 * K + koff;
    const float* Wp = W + (size_t)m0 * K + koff;

    int wr = wid >> 2;          // warp row: 64 token-rows
    int wc = wid & 3;           // warp col: 32 feature-cols
    uint32_t sb = smem_to_u32(sm);

    // ldmatrix lane address offsets (bytes), row stride 80
    uint32_t aOff = (uint32_t)(wr * 64 + (lane & 7) + 8 * ((lane >> 3) & 1)) * 80
                  + ((lane >> 4) & 1) * 16;
    int lm = lane & 15;
    uint32_t bOff = (uint32_t)(wc * 32 + (lm & 7)) * 80 + ((lm >> 3) & 1) * 16;

    // per-thread loader slots: 4 float4 each for A and W
    int lrow = (tid * 4 + 0) >> 3;  // placeholder; computed per i below
    (void)lrow;

    float c[4][4][4];
#pragma unroll
    for (int i = 0; i < 4; i++)
#pragma unroll
        for (int j = 0; j < 4; j++)
#pragma unroll
            for (int q = 0; q < 4; q++) c[i][j][q] = 0.f;

    int NC = Kt >> 5;

    // ---- stage fill helper (macro to keep regs local) ----
#define CONVERT_STORE(stage_base, av, wv)                                      \
    {                                                                          \
        char* stg = sm + (stage_base);                                         \
        _Pragma("unroll")                                                      \
        for (int i = 0; i < 4; i++) {                                          \
            int s = tid + i * 256;                                             \
            int row = s >> 3;                                                  \
            int c4 = (s & 7) * 4;                                              \
            uint32_t byte = (uint32_t)row * 80 + c4 * 2;                       \
            float4 a = av[i], w = wv[i];                                       \
            *(uint2*)(stg + ST_AHI + byte) =                                   \
                make_uint2(h2pack(a.x, a.y), h2pack(a.z, a.w));                \
            uint32_t wh0 = h2pack(w.x, w.y), wh1 = h2pack(w.z, w.w);           \
            __half2 wf0 = *(__half2*)&wh0, wf1 = *(__half2*)&wh1;              \
            float2 f0 = __half22float2(wf0), f1 = __half22float2(wf1);         \
            *(uint2*)(stg + ST_WHI + byte) = make_uint2(wh0, wh1);             \
            *(uint2*)(stg + ST_WLO + byte) =                                   \
                make_uint2(h2pack(w.x - f0.x, w.y - f0.y),                     \
                           h2pack(w.z - f1.x, w.w - f1.y));                    \
        }                                                                      \
    }

    {
        float4 av[4], wv[4];
#pragma unroll
        for (int i = 0; i < 4; i++) {
            int s = tid + i * 256;
            int row = s >> 3;
            int c4 = (s & 7) * 4;
            av[i] = *(const float4*)(Ap + (size_t)row * K + c4);
            wv[i] = *(const float4*)(Wp + (size_t)row * K + c4);
        }
        CONVERT_STORE(0, av, wv);
    }
    __syncthreads();

    for (int ch = 0; ch < NC; ch++) {
        int cur = ch & 1;
        bool has = (ch + 1 < NC);
        float4 av[4], wv[4];
        if (has) {
#pragma unroll
            for (int i = 0; i < 4; i++) {
                int s = tid + i * 256;
                int row = s >> 3;
                int c4 = (s & 7) * 4;
                av[i] = *(const float4*)(Ap + (size_t)row * K + (ch + 1) * 32 + c4);
                wv[i] = *(const float4*)(Wp + (size_t)row * K + (ch + 1) * 32 + c4);
            }
        }
        uint32_t stg = (uint32_t)(cur * ST_STRIDE);
#pragma unroll
        for (int k16 = 0; k16 < 2; k16++) {
            uint32_t kb = k16 * 32;          // 16 fp16 = 32 bytes
            uint32_t ah[4][4];
#pragma unroll
            for (int mi = 0; mi < 4; mi++)
                ldmx4(ah[mi], sb + stg + ST_AHI + aOff + mi * 1280 + kb);
#pragma unroll
            for (int ni = 0; ni < 4; ni++) {
                uint32_t bh[2], bl[2];
                ldmx2(bh, sb + stg + ST_WHI + bOff + ni * 640 + kb);
                ldmx2(bl, sb + stg + ST_WLO + bOff + ni * 640 + kb);
#pragma unroll
                for (int mi = 0; mi < 4; mi++) {
                    mma_fp16(c[mi][ni], ah[mi], bh);
                    mma_fp16(c[mi][ni], ah[mi], bl);
                }
            }
        }
        if (has) {
            CONVERT_STORE((cur ^ 1) * ST_STRIDE, av, wv);
        }
        __syncthreads();
    }
#undef CONVERT_STORE

    // epilogue: D fragment c0..c3 -> rows (g, g+8), cols (2t, 2t+1)
    int g = lane >> 2, t = lane & 3;
    int zrow = blockIdx.z * (gridDim.y << 7);
#pragma unroll
    for (int mi = 0; mi < 4; mi++) {
#pragma unroll
        for (int ni = 0; ni < 4; ni++) {
            int row0 = n0 + wr * 64 + mi * 16 + g;
            int col = m0 + wc * 32 + ni * 8 + t * 2;
            size_t i0 = (size_t)(zrow + row0) * M + col;
            size_t i1 = i0 + (size_t)8 * M;
            float2 v0 = make_float2(c[mi][ni][0], c[mi][ni][1]);
            float2 v1 = make_float2(c[mi][ni][2], c[mi][ni][3]);
            if (MODE == 1) {
                float2 r0 = *(const float2*)&RG[i0];
                float2 r1 = *(const float2*)&RG[i1];
                v0.x += r0.x; v0.y += r0.y; v1.x += r1.x; v1.y += r1.y;
            }
            if (MODE == 2) {
                float2 r0 = *(const float2*)&C[i0];
                float2 r1 = *(const float2*)&C[i1];
                v0.x += r0.x; v0.y += r0.y; v1.x += r1.x; v1.y += r1.y;
            }
            if (MODE == 3) {
                float2 g0 = *(const float2*)&RG[i0];
                float2 g1 = *(const float2*)&RG[i1];
                v0.x *= g0.x / (1.0f + __expf(-g0.x));
                v0.y *= g0.y / (1.0f + __expf(-g0.y));
                v1.x *= g1.x / (1.0f + __expf(-g1.x));
                v1.y *= g1.y / (1.0f + __expf(-g1.y));
            }
            *(float2*)&C[i0] = v0;
            *(float2*)&C[i1] = v1;
        }
    }
}

// ---------------------------------------------------------------------------
// RMSNorm
// ---------------------------------------------------------------------------
__global__ void __launch_bounds__(256) rms_kernel(const float* __restrict__ x,
                                                  const float* __restrict__ w,
                                                  float* __restrict__ out) {
    int n = blockIdx.x;
    int tid = threadIdx.x;
    const float4* xr = (const float4*)(x + (size_t)n * DMODEL);
    float4 loc[2];
    float ss = 0.f;
#pragma unroll
    for (int i = 0; i < 2; i++) {
        float4 v = xr[tid + i * 256];
        loc[i] = v;
        ss += v.x * v.x + v.y * v.y + v.z * v.z + v.w * v.w;
    }
#pragma unroll
    for (int off = 16; off; off >>= 1)
        ss += __shfl_xor_sync(0xffffffffu, ss, off);
    __shared__ float red[8];
    if ((tid & 31) == 0) red[tid >> 5] = ss;
    __syncthreads();
    float tot = red[0] + red[1] + red[2] + red[3] + red[4] + red[5] + red[6] + red[7];
    float inv = rsqrtf(tot * (1.0f / (float)DMODEL) + 1e-5f);
    const float4* w4 = (const float4*)w;
    float4* o4 = (float4*)(out + (size_t)n * DMODEL);
#pragma unroll
    for (int i = 0; i < 2; i++) {
        int idx = tid + i * 256;
        float4 wv = w4[idx];
        float4 v = loc[i];
        o4[idx] = make_float4(v.x * inv * wv.x, v.y * inv * wv.y,
                              v.z * inv * wv.z, v.w * inv * wv.w);
    }
}

// ---------------------------------------------------------------------------
// qkv weight concat: wc = [q_V(1536x2048); k_V(384x2048); v_V(384x2048)]
// ---------------------------------------------------------------------------
__global__ void __launch_bounds__(256) concat_qkv(const float* __restrict__ q,
                                                  const float* __restrict__ k,
                                                  const float* __restrict__ v,
                                                  float* __restrict__ wc) {
    int i = blockIdx.x * 256 + threadIdx.x;
    float4 val;
    if (i < 786432) val = ((const float4*)q)[i];
    else if (i < 983040) val = ((const float4*)k)[i - 786432];
    else val = ((const float4*)v)[i - 983040];
    ((float4*)wc)[i] = val;
}

// ---------------------------------------------------------------------------
// split-K reduce: dst[i] = sum_{p<8} part[p*262144 + i]   (256x1024 floats)
// ---------------------------------------------------------------------------
__global__ void __launch_bounds__(256) reduce8_kernel(const float* __restrict__ part,
                                                      float* __restrict__ dst) {
    int i = blockIdx.x * 256 + threadIdx.x;
    const float4* p = (const float4*)part;
    float4 s = p[i];
#pragma unroll
    for (int j = 1; j < 8; j++) {
        float4 v = p[i + j * 65536];
        s.x += v.x; s.y += v.y; s.z += v.z; s.w += v.w;
    }
    ((float4*)dst)[i] = s;
}

// ---------------------------------------------------------------------------
// Batched per-head Us projection + fused RoPE (R6 version).
// ---------------------------------------------------------------------------
__global__ void __launch_bounds__(256) proj2_kernel(
    const float* __restrict__ Rv,
    const float* __restrict__ q_Us, const float* __restrict__ k_Us,
    const float* __restrict__ v_Us,
    const int* __restrict__ pos_ids,
    float* __restrict__ qb, float* __restrict__ kb, float* __restrict__ vb) {
    int hidx = blockIdx.y;
    int n0 = blockIdx.x * 128;
    int tid = threadIdx.x;
    __shared__ float Rvs[48][128];
    __shared__ float Uss[48][64];

#pragma unroll
    for (int i = 0; i < 6; i++) {
        int f = tid + i * 256;
        int r = f / 12, c4 = (f % 12) * 4;
        float4 v = *(const float4*)&Rv[(size_t)(n0 + r) * 2304 + hidx * 48 + c4];
        Rvs[c4 + 0][r] = v.x; Rvs[c4 + 1][r] = v.y;
        Rvs[c4 + 2][r] = v.z; Rvs[c4 + 3][r] = v.w;
    }
    const float* Us = (hidx < 32) ? q_Us + (size_t)hidx * 3072
                    : (hidx < 40) ? k_Us + (size_t)(hidx - 32) * 3072
                                  : v_Us + (size_t)(hidx - 40) * 3072;
#pragma unroll
    for (int i = 0; i < 3; i++) {
        int f = tid + i * 256;
        int dh = f / 12, c4 = (f % 12) * 4;
        float4 v = *(const float4*)&Us[dh * 48 + c4];
        Uss[c4 + 0][dh] = v.x; Uss[c4 + 1][dh] = v.y;
        Uss[c4 + 2][dh] = v.z; Uss[c4 + 3][dh] = v.w;
    }
    __syncthreads();

    int tx = tid & 7;
    int ty = tid >> 3;
    float acc[4][8];
#pragma unroll
    for (int i = 0; i < 4; i++)
#pragma unroll
        for (int j = 0; j < 8; j++) acc[i][j] = 0.f;

#pragma unroll 8
    for (int k = 0; k < 48; k++) {
        float4 a = *(const float4*)&Rvs[k][ty * 4];
        float4 w0 = *(const float4*)&Uss[k][tx * 8];
        float4 w1 = *(const float4*)&Uss[k][tx * 8 + 4];
        float av[4] = {a.x, a.y, a.z, a.w};
        float wv[8] = {w0.x, w0.y, w0.z, w0.w, w1.x, w1.y, w1.z, w1.w};
#pragma unroll
        for (int i = 0; i < 4; i++)
#pragma unroll
            for (int j = 0; j < 8; j++) acc[i][j] += av[i] * wv[j];
    }

    float prt[4][8];
#pragma unroll
    for (int i = 0; i < 4; i++)
#pragma unroll
        for (int j = 0; j < 8; j++)
            prt[i][j] = __shfl_xor_sync(0xffffffffu, acc[i][j], 4);

    bool dorope = (hidx < 40);
    float sgn = (tx < 4) ? -1.f : 1.f;
    float invf[4];
    if (dorope) {
#pragma unroll
        for (int fj = 0; fj < 4; fj++)
            invf[fj] = expf(-(float)(tx * 4 + fj) * (9.210340371976184f / 32.0f));
    }

    float* outp;
    int hh, nh;
    if (hidx < 32)      { outp = qb; hh = hidx;      nh = NH;  }
    else if (hidx < 40) { outp = kb; hh = hidx - 32; nh = NHK; }
    else                { outp = vb; hh = hidx - 40; nh = NHK; }

#pragma unroll
    for (int i = 0; i < 4; i++) {
        int n = n0 + ty * 4 + i;
        int b = n >> 10;
        int t = n & 1023;
        float vals[8];
        if (dorope) {
            float pos = (float)pos_ids[t];
#pragma unroll
            for (int fj = 0; fj < 4; fj++) {
                float ang = pos * invf[fj];
                float c = cosf(ang), s = sinf(ang);
                vals[fj * 2 + 0] = acc[i][fj * 2 + 0] * c + sgn * prt[i][fj * 2 + 0] * s;
                vals[fj * 2 + 1] = acc[i][fj * 2 + 1] * c + sgn * prt[i][fj * 2 + 1] * s;
            }
        } else {
#pragma unroll
            for (int j = 0; j < 8; j++) vals[j] = acc[i][j];
        }
        float* op = outp + (((size_t)b * nh + hh) * TSEQ + t) * DHEAD + tx * 8;
        *(float4*)op       = make_float4(vals[0], vals[1], vals[2], vals[3]);
        *(float4*)(op + 4) = make_float4(vals[4], vals[5], vals[6], vals[7]);
    }
}

// ---------------------------------------------------------------------------
// Causal flash attention, packed f32x2 + __expf (R6 version).
// ---------------------------------------------------------------------------
__global__ void __launch_bounds__(128) flash_kernel(const float* __restrict__ Q,
                                                    const float* __restrict__ Kg,
                                                    const float* __restrict__ Vg,
                                                    float* __restrict__ Out) {
    int bh = blockIdx.y;
    int b = bh >> 5;
    int h = bh & 31;
    int hk = h >> 2;
    int q0 = blockIdx.x * 128;
    int tid = threadIdx.x;
    int qi = q0 + tid;

    __shared__ __align__(16) float Ks[32][64];
    __shared__ __align__(16) float Vs[32][64];

    ull q2[32];
    const float* qp = Q + (((size_t)b * NH + h) * TSEQ + qi) * DHEAD;
#pragma unroll
    for (int c = 0; c < 16; c++) {
        ulonglong2 t = *(const ulonglong2*)(qp + c * 4);
        q2[c * 2] = t.x; q2[c * 2 + 1] = t.y;
    }
    float m = -1e30f, l = 0.f;
    ull o2[32];
#pragma unroll
    for (int d = 0; d < 32; d++) o2[d] = 0ull;

    const float* kbase = Kg + (((size_t)b * NHK + hk) * TSEQ) * DHEAD;
    const float* vbase = Vg + (((size_t)b * NHK + hk) * TSEQ) * DHEAD;
    int nkt = (q0 + 128) / 32;

    for (int kt = 0; kt < nkt; kt++) {
        int kstart = kt * 32;
        __syncthreads();
#pragma unroll
        for (int i = 0; i < 4; i++) {
            int e = tid + i * 128;
            int row = e >> 4;
            int col = (e & 15) * 4;
            *(float4*)&Ks[row][col] = *(const float4*)(kbase + (size_t)(kstart + row) * 64 + col);
            *(float4*)&Vs[row][col] = *(const float4*)(vbase + (size_t)(kstart + row) * 64 + col);
        }
        __syncthreads();

        float s[32];
#pragma unroll
        for (int j = 0; j < 32; j++) {
            ull a0 = 0ull, a1 = 0ull, a2 = 0ull, a3 = 0ull;
#pragma unroll
            for (int c = 0; c < 8; c++) {
                ulonglong2 k01 = *(const ulonglong2*)&Ks[j][c * 8];
                ulonglong2 k23 = *(const ulonglong2*)&Ks[j][c * 8 + 4];
                fma2(a0, q2[c * 4 + 0], k01.x);
                fma2(a1, q2[c * 4 + 1], k01.y);
                fma2(a2, q2[c * 4 + 2], k23.x);
                fma2(a3, q2[c * 4 + 3], k23.y);
            }
            float2 f0 = upk2(a0), f1 = upk2(a1), f2 = upk2(a2), f3 = upk2(a3);
            float acc = ((f0.x + f0.y) + (f1.x + f1.y)) +
                        ((f2.x + f2.y) + (f3.x + f3.y));
            s[j] = (kstart + j <= qi) ? acc * 0.125f : -1e30f;
        }
        float mt = m;
#pragma unroll
        for (int j = 0; j < 32; j++) mt = fmaxf(mt, s[j]);
        float corr = __expf(m - mt);
        m = mt;
        l *= corr;
        ull c2 = pk2(corr);
#pragma unroll
        for (int d = 0; d < 32; d++) mul2(o2[d], c2);
#pragma unroll
        for (int j = 0; j < 32; j++) {
            float p = __expf(s[j] - m);
            l += p;
            ull p2 = pk2(p);
#pragma unroll
            for (int c = 0; c < 8; c++) {
                ulonglong2 v01 = *(const ulonglong2*)&Vs[j][c * 8];
                ulonglong2 v23 = *(const ulonglong2*)&Vs[j][c * 8 + 4];
                fma2(o2[c * 4 + 0], p2, v01.x);
                fma2(o2[c * 4 + 1], p2, v01.y);
                fma2(o2[c * 4 + 2], p2, v23.x);
                fma2(o2[c * 4 + 3], p2, v23.y);
            }
        }
    }
    float invl = 1.0f / l;
    float* op = Out + ((size_t)b * TSEQ + qi) * DMODEL + h * DHEAD;
#pragma unroll
    for (int d = 0; d < 32; d++) {
        float2 v = upk2(o2[d]);
        *(float2*)(op + d * 2) = make_float2(v.x * invl, v.y * invl);
    }
}

// ---------------------------------------------------------------------------
// Launch
// ---------------------------------------------------------------------------
extern "C" void kernel_launch(void* const* d_in, const int* in_sizes, int n_in,
                              void* d_out, int out_size) {
    const float* x     = (const float*)d_in[0];
    const int*   pos   = (const int*)d_in[1];
    const float* ln1   = (const float*)d_in[2];
    const float* ln2   = (const float*)d_in[3];
    const float* q_Us  = (const float*)d_in[4];
    const float* q_V   = (const float*)d_in[5];
    const float* k_Us  = (const float*)d_in[6];
    const float* k_V   = (const float*)d_in[7];
    const float* v_Us  = (const float*)d_in[8];
    const float* v_V   = (const float*)d_in[9];
    const float* o_Us  = (const float*)d_in[10];
    const float* o_V   = (const float*)d_in[11];
    const float* g_Us  = (const float*)d_in[12];
    const float* g_V   = (const float*)d_in[13];
    const float* u_Us  = (const float*)d_in[14];
    const float* u_V   = (const float*)d_in[15];
    const float* d_Us  = (const float*)d_in[16];
    const float* d_V   = (const float*)d_in[17];
    float* out = (float*)d_out;

    cudaFuncSetAttribute(mmfp16<0>, cudaFuncAttributeMaxDynamicSharedMemorySize, MM_SMEM);
    cudaFuncSetAttribute(mmfp16<1>, cudaFuncAttributeMaxDynamicSharedMemorySize, MM_SMEM);
    cudaFuncSetAttribute(mmfp16<2>, cudaFuncAttributeMaxDynamicSharedMemorySize, MM_SMEM);
    cudaFuncSetAttribute(mmfp16<3>, cudaFuncAttributeMaxDynamicSharedMemorySize, MM_SMEM);

    float* S = nullptr;
    cudaGetSymbolAddress((void**)&S, g_scratch);
    float* H  = S + OFF_H;
    float* Bb = S + OFF_B;
    float* C  = S + OFF_C;

    float* hbuf  = H;
    float* wc    = C;                        // 2304x2048
    float* qkvr  = Bb;                       // 2048x2304
    float* qb    = C;                        // 2*32*1024*64   (wc dead)
    float* kb    = C + 4194304;              // 2*8*1024*64
    float* vb    = C + 5242880;              // 2*8*1024*64
    float* attn  = H;                        // 2048x2048      (hbuf dead)
    float* ar    = Bb;                       // 2048x1024      (qkvr dead)
    float* gr    = Bb;                       // 2048x1024      (ar dead)
    float* ur    = Bb + 2097152;             // 2048x1024
    float* gate  = C;                        // 256x8192       (qb/kb/vb dead)
    float* inner = C + 2097152;              // 256x8192
    float* part  = C + 4194304;              // 8 x 256x1024
    float* dr    = H;                        // 2048x1024      (hbuf dead)

    // ---- attention sub-block ----
    rms_kernel<<<NTOK, 256>>>(x, ln1, hbuf);
    concat_qkv<<<4608, 256>>>(q_V, k_V, v_V, wc);
    mmfp16<0><<<dim3(18, 16), 256, MM_SMEM>>>(hbuf, wc, nullptr, qkvr, 2304, 2048, 2048);
    proj2_kernel<<<dim3(16, 48), 256>>>(qkvr, q_Us, k_Us, v_Us, pos, qb, kb, vb);
    flash_kernel<<<dim3(8, 64), 128>>>(qb, kb, vb, attn);
    mmfp16<0><<<dim3(8, 16), 256, MM_SMEM>>>(attn, o_V, nullptr, ar, 1024, 2048, 2048);
    mmfp16<1><<<dim3(16, 16), 256, MM_SMEM>>>(ar, o_Us, x, out, 2048, 1024, 1024);

    // ---- MLP sub-block ----
    rms_kernel<<<NTOK, 256>>>(out, ln2, hbuf);
    mmfp16<0><<<dim3(8, 16), 256, MM_SMEM>>>(hbuf, g_V, nullptr, gr, 1024, 2048, 2048);
    mmfp16<0><<<dim3(8, 16), 256, MM_SMEM>>>(hbuf, u_V, nullptr, ur, 1024, 2048, 2048);

    for (int c = 0; c < NTOK / NCHUNK; c++) {
        const float* grc = gr + (size_t)c * NCHUNK * 1024;
        const float* urc = ur + (size_t)c * NCHUNK * 1024;
        float* drc = dr + (size_t)c * NCHUNK * 1024;
        mmfp16<0><<<dim3(64, 2), 256, MM_SMEM>>>(grc, g_Us, nullptr, gate, 8192, 1024, 1024);
        mmfp16<3><<<dim3(64, 2), 256, MM_SMEM>>>(urc, u_Us, gate, inner, 8192, 1024, 1024);
        mmfp16<0><<<dim3(8, 2, 8), 256, MM_SMEM>>>(inner, d_V, nullptr, part, 1024, 8192, 1024);
        reduce8_kernel<<<256, 256>>>(part, drc);
    }
    mmfp16<2><<<dim3(16, 16), 256, MM_SMEM>>>(dr, d_Us, nullptr, out, 2048, 1024, 1024);
}

// round 16
// speedup vs baseline: 1.0295x; 1.0295x over previous
#include <cuda_runtime.h>
#include <cuda_fp16.h>
#include <cstdint>

// ---------------------------------------------------------------------------
// FlashSVDLlamaBlock R16: fp16 2-pass split GEMM, BK=64 (one sync per 64-K),
// split-half loader, merged gV/uV launch. tcgen05 unavailable (compute_103).
//   B=2, T=1024, D=2048, H=32, HK=8, DH=64, R=48, RO=RFF=1024, INTER=8192
// Scratch (61 MB, phase-liveness reuse):
//   H [0..4,194,303]: hbuf -> attn -> hbuf -> dr
//   B [4,194,304..8,912,895]: qkvr -> ar -> gu
//   C [8,912,896..15,204,351]: wc -> qb/kb/vb -> wguv -> gate|inner|part
// ---------------------------------------------------------------------------

#define NTOK 2048
#define DMODEL 2048
#define NH 32
#define NHK 8
#define DHEAD 64
#define RNK 48
#define TSEQ 1024
#define NCHUNK 256

#define OFF_H 0u
#define OFF_B 4194304u
#define OFF_C 8912896u
#define SCRATCH_TOTAL 15204352u

__device__ float g_scratch[SCRATCH_TOTAL];

typedef unsigned long long ull;

// ---- packed f32x2 helpers (flash attention) --------------------------------
__device__ __forceinline__ ull pk2(float v) {
    ull r; asm("mov.b64 %0, {%1, %1};" : "=l"(r) : "f"(v)); return r;
}
__device__ __forceinline__ void fma2(ull& c, ull a, ull b) {
    asm("fma.rn.f32x2 %0, %1, %2, %0;" : "+l"(c) : "l"(a), "l"(b));
}
__device__ __forceinline__ void mul2(ull& c, ull a) {
    asm("mul.rn.f32x2 %0, %0, %1;" : "+l"(c) : "l"(a));
}
__device__ __forceinline__ float2 upk2(ull v) {
    float2 r; asm("mov.b64 {%0, %1}, %2;" : "=f"(r.x), "=f"(r.y) : "l"(v)); return r;
}

// ---- tensor-core helpers (base ISA, sm_80+) --------------------------------
__device__ __forceinline__ uint32_t smem_to_u32(const void* p) {
    uint32_t a;
    asm("{ .reg .u64 t; cvta.to.shared.u64 t, %1; cvt.u32.u64 %0, t; }"
        : "=r"(a) : "l"(p));
    return a;
}
__device__ __forceinline__ void ldmx4(uint32_t* r, uint32_t addr) {
    asm volatile("ldmatrix.sync.aligned.m8n8.x4.shared.b16 {%0,%1,%2,%3}, [%4];"
                 : "=r"(r[0]), "=r"(r[1]), "=r"(r[2]), "=r"(r[3]) : "r"(addr));
}
__device__ __forceinline__ void ldmx2(uint32_t* r, uint32_t addr) {
    asm volatile("ldmatrix.sync.aligned.m8n8.x2.shared.b16 {%0,%1}, [%2];"
                 : "=r"(r[0]), "=r"(r[1]) : "r"(addr));
}
__device__ __forceinline__ void mma_fp16(float* c, const uint32_t* a,
                                         const uint32_t* b) {
    asm volatile(
        "mma.sync.aligned.m16n8k16.row.col.f32.f16.f16.f32 "
        "{%0,%1,%2,%3}, {%4,%5,%6,%7}, {%8,%9}, {%0,%1,%2,%3};"
        : "+f"(c[0]), "+f"(c[1]), "+f"(c[2]), "+f"(c[3])
        : "r"(a[0]), "r"(a[1]), "r"(a[2]), "r"(a[3]), "r"(b[0]), "r"(b[1]));
}
__device__ __forceinline__ uint32_t h2pack(float x, float y) {
    __half2 h = __float22half2_rn(make_float2(x, y));
    return *(uint32_t*)&h;
}

// ---------------------------------------------------------------------------
// mmfp16: C[n,m] = sum_k A[n,k]*W[m,k], tensor cores, fp16 2-pass split:
//   C ≈ A_hi·W_hi + A_hi·W_lo
//   MODE 0: C = d;  1: C = d + RG[n,m];  2: C += d;  3: C = silu(RG[n,m]) * d
// Tile 128(tok) x 128(feat), 8 warps (2x4), warp tile 64x32, BK=64.
// One __syncthreads per 64-K chunk; loader split in K-halves to bound regs.
// Smem rows stride 144 B (16B-aligned rows, conflict-free LDSM).
// A row stride = lda (A may be a column slice of a wider matrix).
// Split-K via blockIdx.z (range Kt, out rows offset z*gridDim.y*128, MODE 0).
// ---------------------------------------------------------------------------
#define ST_AHI 0
#define ST_WHI 18432
#define ST_WLO 36864
#define ST_STRIDE 55296
#define MM_SMEM 110592

template <int MODE>
__global__ void __launch_bounds__(256, 2) mmfp16(const float* __restrict__ A,
                                                 const float* __restrict__ W,
                                                 const float* __restrict__ RG,
                                                 float* __restrict__ C,
                                                 int M, int K, int Kt, int lda) {
    extern __shared__ __align__(16) char sm[];
    int tid = threadIdx.x;
    int wid = tid >> 5, lane = tid & 31;
    int m0 = blockIdx.x * 128, n0 = blockIdx.y * 128;
    size_t koff = (size_t)blockIdx.z * Kt;
    const float* Ap = A + (size_t)n0 * lda + koff;
    const float* Wp = W + (size_t)m0 * K + koff;

    int wr = wid >> 2;          // warp row: 64 token-rows
    int wc = wid & 3;           // warp col: 32 feature-cols
    uint32_t sb = smem_to_u32(sm);

    // ldmatrix lane address offsets (bytes), row stride 144
    uint32_t aOff = (uint32_t)(wr * 64 + (lane & 7) + 8 * ((lane >> 3) & 1)) * 144
                  + ((lane >> 4) & 1) * 16;
    int lm = lane & 15;
    uint32_t bOff = (uint32_t)(wc * 32 + (lm & 7)) * 144 + ((lm >> 3) & 1) * 16;

    float c[4][4][4];
#pragma unroll
    for (int i = 0; i < 4; i++)
#pragma unroll
        for (int j = 0; j < 4; j++)
#pragma unroll
            for (int q = 0; q < 4; q++) c[i][j][q] = 0.f;

    int NC = Kt >> 6;

    // load one K-half (32 cols) of next chunk: 4 float4 per matrix per thread
#define LDG_HALF(av, wv, kcol)                                                 \
    _Pragma("unroll")                                                          \
    for (int i = 0; i < 4; i++) {                                              \
        int s = tid + i * 256;                                                 \
        int row = s >> 3;                                                      \
        int c4 = (s & 7) * 4;                                                  \
        av[i] = *(const float4*)(Ap + (size_t)row * lda + (kcol) + c4);        \
        wv[i] = *(const float4*)(Wp + (size_t)row * K + (kcol) + c4);          \
    }

#define CVT_STS(stage_base, halfoff, av, wv)                                   \
    {                                                                          \
        char* stg = sm + (stage_base);                                         \
        _Pragma("unroll")                                                      \
        for (int i = 0; i < 4; i++) {                                          \
            int s = tid + i * 256;                                             \
            int row = s >> 3;                                                  \
            int c4 = (s & 7) * 4;                                              \
            uint32_t byte = (uint32_t)row * 144 + ((halfoff) + c4) * 2;        \
            float4 a = av[i], w = wv[i];                                       \
            *(uint2*)(stg + ST_AHI + byte) =                                   \
                make_uint2(h2pack(a.x, a.y), h2pack(a.z, a.w));                \
            uint32_t wh0 = h2pack(w.x, w.y), wh1 = h2pack(w.z, w.w);           \
            __half2 wf0 = *(__half2*)&wh0, wf1 = *(__half2*)&wh1;              \
            float2 f0 = __half22float2(wf0), f1 = __half22float2(wf1);         \
            *(uint2*)(stg + ST_WHI + byte) = make_uint2(wh0, wh1);             \
            *(uint2*)(stg + ST_WLO + byte) =                                   \
                make_uint2(h2pack(w.x - f0.x, w.y - f0.y),                     \
                           h2pack(w.z - f1.x, w.w - f1.y));                    \
        }                                                                      \
    }

#define MMA_K16(stg, k16)                                                      \
    {                                                                          \
        uint32_t kb = (k16) * 32;                                              \
        uint32_t ah[4][4];                                                     \
        _Pragma("unroll")                                                      \
        for (int mi = 0; mi < 4; mi++)                                         \
            ldmx4(ah[mi], sb + (stg) + ST_AHI + aOff + mi * 2304 + kb);        \
        _Pragma("unroll")                                                      \
        for (int ni = 0; ni < 4; ni++) {                                       \
            uint32_t bh[2], bl[2];                                             \
            ldmx2(bh, sb + (stg) + ST_WHI + bOff + ni * 1152 + kb);            \
            ldmx2(bl, sb + (stg) + ST_WLO + bOff + ni * 1152 + kb);            \
            _Pragma("unroll")                                                  \
            for (int mi = 0; mi < 4; mi++) {                                   \
                mma_fp16(c[mi][ni], ah[mi], bh);                               \
                mma_fp16(c[mi][ni], ah[mi], bl);                               \
            }                                                                  \
        }                                                                      \
    }

    // prologue: fill stage 0 (both halves)
    {
        float4 av[4], wv[4];
        LDG_HALF(av, wv, 0);
        CVT_STS(0, 0, av, wv);
        LDG_HALF(av, wv, 32);
        CVT_STS(0, 32, av, wv);
    }
    __syncthreads();

    for (int ch = 0; ch < NC; ch++) {
        int cur = ch & 1;
        bool has = (ch + 1 < NC);
        uint32_t stg = (uint32_t)(cur * ST_STRIDE);
        uint32_t nxt = (uint32_t)((cur ^ 1) * ST_STRIDE);
        float4 av[4], wv[4];
        if (has) LDG_HALF(av, wv, (ch + 1) * 64);
        MMA_K16(stg, 0);
        MMA_K16(stg, 1);
        if (has) {
            CVT_STS(nxt, 0, av, wv);
            LDG_HALF(av, wv, (ch + 1) * 64 + 32);
        }
        MMA_K16(stg, 2);
        MMA_K16(stg, 3);
        if (has) CVT_STS(nxt, 32, av, wv);
        __syncthreads();
    }
#undef LDG_HALF
#undef CVT_STS
#undef MMA_K16

    // epilogue: D fragment c0..c3 -> rows (g, g+8), cols (2t, 2t+1)
    int g = lane >> 2, t = lane & 3;
    int zrow = blockIdx.z * (gridDim.y << 7);
#pragma unroll
    for (int mi = 0; mi < 4; mi++) {
#pragma unroll
        for (int ni = 0; ni < 4; ni++) {
            int row0 = n0 + wr * 64 + mi * 16 + g;
            int col = m0 + wc * 32 + ni * 8 + t * 2;
            size_t i0 = (size_t)(zrow + row0) * M + col;
            size_t i1 = i0 + (size_t)8 * M;
            float2 v0 = make_float2(c[mi][ni][0], c[mi][ni][1]);
            float2 v1 = make_float2(c[mi][ni][2], c[mi][ni][3]);
            if (MODE == 1) {
                float2 r0 = *(const float2*)&RG[i0];
                float2 r1 = *(const float2*)&RG[i1];
                v0.x += r0.x; v0.y += r0.y; v1.x += r1.x; v1.y += r1.y;
            }
            if (MODE == 2) {
                float2 r0 = *(const float2*)&C[i0];
                float2 r1 = *(const float2*)&C[i1];
                v0.x += r0.x; v0.y += r0.y; v1.x += r1.x; v1.y += r1.y;
            }
            if (MODE == 3) {
                float2 g0 = *(const float2*)&RG[i0];
                float2 g1 = *(const float2*)&RG[i1];
                v0.x *= g0.x / (1.0f + __expf(-g0.x));
                v0.y *= g0.y / (1.0f + __expf(-g0.y));
                v1.x *= g1.x / (1.0f + __expf(-g1.x));
                v1.y *= g1.y / (1.0f + __expf(-g1.y));
            }
            *(float2*)&C[i0] = v0;
            *(float2*)&C[i1] = v1;
        }
    }
}

// ---------------------------------------------------------------------------
// RMSNorm
// ---------------------------------------------------------------------------
__global__ void __launch_bounds__(256) rms_kernel(const float* __restrict__ x,
                                                  const float* __restrict__ w,
                                                  float* __restrict__ out) {
    int n = blockIdx.x;
    int tid = threadIdx.x;
    const float4* xr = (const float4*)(x + (size_t)n * DMODEL);
    float4 loc[2];
    float ss = 0.f;
#pragma unroll
    for (int i = 0; i < 2; i++) {
        float4 v = xr[tid + i * 256];
        loc[i] = v;
        ss += v.x * v.x + v.y * v.y + v.z * v.z + v.w * v.w;
    }
#pragma unroll
    for (int off = 16; off; off >>= 1)
        ss += __shfl_xor_sync(0xffffffffu, ss, off);
    __shared__ float red[8];
    if ((tid & 31) == 0) red[tid >> 5] = ss;
    __syncthreads();
    float tot = red[0] + red[1] + red[2] + red[3] + red[4] + red[5] + red[6] + red[7];
    float inv = rsqrtf(tot * (1.0f / (float)DMODEL) + 1e-5f);
    const float4* w4 = (const float4*)w;
    float4* o4 = (float4*)(out + (size_t)n * DMODEL);
#pragma unroll
    for (int i = 0; i < 2; i++) {
        int idx = tid + i * 256;
        float4 wv = w4[idx];
        float4 v = loc[i];
        o4[idx] = make_float4(v.x * inv * wv.x, v.y * inv * wv.y,
                              v.z * inv * wv.z, v.w * inv * wv.w);
    }
}

// ---------------------------------------------------------------------------
// qkv weight concat: wc = [q_V(1536x2048); k_V(384x2048); v_V(384x2048)]
// ---------------------------------------------------------------------------
__global__ void __launch_bounds__(256) concat_qkv(const float* __restrict__ q,
                                                  const float* __restrict__ k,
                                                  const float* __restrict__ v,
                                                  float* __restrict__ wc) {
    int i = blockIdx.x * 256 + threadIdx.x;
    float4 val;
    if (i < 786432) val = ((const float4*)q)[i];
    else if (i < 983040) val = ((const float4*)k)[i - 786432];
    else val = ((const float4*)v)[i - 983040];
    ((float4*)wc)[i] = val;
}

// ---------------------------------------------------------------------------
// gate/up weight concat: wguv = [g_V(1024x2048); u_V(1024x2048)]
// ---------------------------------------------------------------------------
__global__ void __launch_bounds__(256) concat_guv(const float* __restrict__ gw,
                                                  const float* __restrict__ uw,
                                                  float* __restrict__ wguv) {
    int i = blockIdx.x * 256 + threadIdx.x;     // float4 index, total 1,048,576
    float4 val = (i < 524288) ? ((const float4*)gw)[i]
                              : ((const float4*)uw)[i - 524288];
    ((float4*)wguv)[i] = val;
}

// ---------------------------------------------------------------------------
// split-K reduce: dst[i] = sum_{p<8} part[p*262144 + i]   (256x1024 floats)
// ---------------------------------------------------------------------------
__global__ void __launch_bounds__(256) reduce8_kernel(const float* __restrict__ part,
                                                      float* __restrict__ dst) {
    int i = blockIdx.x * 256 + threadIdx.x;
    const float4* p = (const float4*)part;
    float4 s = p[i];
#pragma unroll
    for (int j = 1; j < 8; j++) {
        float4 v = p[i + j * 65536];
        s.x += v.x; s.y += v.y; s.z += v.z; s.w += v.w;
    }
    ((float4*)dst)[i] = s;
}

// ---------------------------------------------------------------------------
// Batched per-head Us projection + fused RoPE (R6 version).
// ---------------------------------------------------------------------------
__global__ void __launch_bounds__(256) proj2_kernel(
    const float* __restrict__ Rv,
    const float* __restrict__ q_Us, const float* __restrict__ k_Us,
    const float* __restrict__ v_Us,
    const int* __restrict__ pos_ids,
    float* __restrict__ qb, float* __restrict__ kb, float* __restrict__ vb) {
    int hidx = blockIdx.y;
    int n0 = blockIdx.x * 128;
    int tid = threadIdx.x;
    __shared__ float Rvs[48][128];
    __shared__ float Uss[48][64];

#pragma unroll
    for (int i = 0; i < 6; i++) {
        int f = tid + i * 256;
        int r = f / 12, c4 = (f % 12) * 4;
        float4 v = *(const float4*)&Rv[(size_t)(n0 + r) * 2304 + hidx * 48 + c4];
        Rvs[c4 + 0][r] = v.x; Rvs[c4 + 1][r] = v.y;
        Rvs[c4 + 2][r] = v.z; Rvs[c4 + 3][r] = v.w;
    }
    const float* Us = (hidx < 32) ? q_Us + (size_t)hidx * 3072
                    : (hidx < 40) ? k_Us + (size_t)(hidx - 32) * 3072
                                  : v_Us + (size_t)(hidx - 40) * 3072;
#pragma unroll
    for (int i = 0; i < 3; i++) {
        int f = tid + i * 256;
        int dh = f / 12, c4 = (f % 12) * 4;
        float4 v = *(const float4*)&Us[dh * 48 + c4];
        Uss[c4 + 0][dh] = v.x; Uss[c4 + 1][dh] = v.y;
        Uss[c4 + 2][dh] = v.z; Uss[c4 + 3][dh] = v.w;
    }
    __syncthreads();

    int tx = tid & 7;
    int ty = tid >> 3;
    float acc[4][8];
#pragma unroll
    for (int i = 0; i < 4; i++)
#pragma unroll
        for (int j = 0; j < 8; j++) acc[i][j] = 0.f;

#pragma unroll 8
    for (int k = 0; k < 48; k++) {
        float4 a = *(const float4*)&Rvs[k][ty * 4];
        float4 w0 = *(const float4*)&Uss[k][tx * 8];
        float4 w1 = *(const float4*)&Uss[k][tx * 8 + 4];
        float av[4] = {a.x, a.y, a.z, a.w};
        float wv[8] = {w0.x, w0.y, w0.z, w0.w, w1.x, w1.y, w1.z, w1.w};
#pragma unroll
        for (int i = 0; i < 4; i++)
#pragma unroll
            for (int j = 0; j < 8; j++) acc[i][j] += av[i] * wv[j];
    }

    float prt[4][8];
#pragma unroll
    for (int i = 0; i < 4; i++)
#pragma unroll
        for (int j = 0; j < 8; j++)
            prt[i][j] = __shfl_xor_sync(0xffffffffu, acc[i][j], 4);

    bool dorope = (hidx < 40);
    float sgn = (tx < 4) ? -1.f : 1.f;
    float invf[4];
    if (dorope) {
#pragma unroll
        for (int fj = 0; fj < 4; fj++)
            invf[fj] = expf(-(float)(tx * 4 + fj) * (9.210340371976184f / 32.0f));
    }

    float* outp;
    int hh, nh;
    if (hidx < 32)      { outp = qb; hh = hidx;      nh = NH;  }
    else if (hidx < 40) { outp = kb; hh = hidx - 32; nh = NHK; }
    else                { outp = vb; hh = hidx - 40; nh = NHK; }

#pragma unroll
    for (int i = 0; i < 4; i++) {
        int n = n0 + ty * 4 + i;
        int b = n >> 10;
        int t = n & 1023;
        float vals[8];
        if (dorope) {
            float pos = (float)pos_ids[t];
#pragma unroll
            for (int fj = 0; fj < 4; fj++) {
                float ang = pos * invf[fj];
                float c = cosf(ang), s = sinf(ang);
                vals[fj * 2 + 0] = acc[i][fj * 2 + 0] * c + sgn * prt[i][fj * 2 + 0] * s;
                vals[fj * 2 + 1] = acc[i][fj * 2 + 1] * c + sgn * prt[i][fj * 2 + 1] * s;
            }
        } else {
#pragma unroll
            for (int j = 0; j < 8; j++) vals[j] = acc[i][j];
        }
        float* op = outp + (((size_t)b * nh + hh) * TSEQ + t) * DHEAD + tx * 8;
        *(float4*)op       = make_float4(vals[0], vals[1], vals[2], vals[3]);
        *(float4*)(op + 4) = make_float4(vals[4], vals[5], vals[6], vals[7]);
    }
}

// ---------------------------------------------------------------------------
// Causal flash attention, packed f32x2 + __expf (R6 version).
// ---------------------------------------------------------------------------
__global__ void __launch_bounds__(128) flash_kernel(const float* __restrict__ Q,
                                                    const float* __restrict__ Kg,
                                                    const float* __restrict__ Vg,
                                                    float* __restrict__ Out) {
    int bh = blockIdx.y;
    int b = bh >> 5;
    int h = bh & 31;
    int hk = h >> 2;
    int q0 = blockIdx.x * 128;
    int tid = threadIdx.x;
    int qi = q0 + tid;

    __shared__ __align__(16) float Ks[32][64];
    __shared__ __align__(16) float Vs[32][64];

    ull q2[32];
    const float* qp = Q + (((size_t)b * NH + h) * TSEQ + qi) * DHEAD;
#pragma unroll
    for (int c = 0; c < 16; c++) {
        ulonglong2 t = *(const ulonglong2*)(qp + c * 4);
        q2[c * 2] = t.x; q2[c * 2 + 1] = t.y;
    }
    float m = -1e30f, l = 0.f;
    ull o2[32];
#pragma unroll
    for (int d = 0; d < 32; d++) o2[d] = 0ull;

    const float* kbase = Kg + (((size_t)b * NHK + hk) * TSEQ) * DHEAD;
    const float* vbase = Vg + (((size_t)b * NHK + hk) * TSEQ) * DHEAD;
    int nkt = (q0 + 128) / 32;

    for (int kt = 0; kt < nkt; kt++) {
        int kstart = kt * 32;
        __syncthreads();
#pragma unroll
        for (int i = 0; i < 4; i++) {
            int e = tid + i * 128;
            int row = e >> 4;
            int col = (e & 15) * 4;
            *(float4*)&Ks[row][col] = *(const float4*)(kbase + (size_t)(kstart + row) * 64 + col);
            *(float4*)&Vs[row][col] = *(const float4*)(vbase + (size_t)(kstart + row) * 64 + col);
        }
        __syncthreads();

        float s[32];
#pragma unroll
        for (int j = 0; j < 32; j++) {
            ull a0 = 0ull, a1 = 0ull, a2 = 0ull, a3 = 0ull;
#pragma unroll
            for (int c = 0; c < 8; c++) {
                ulonglong2 k01 = *(const ulonglong2*)&Ks[j][c * 8];
                ulonglong2 k23 = *(const ulonglong2*)&Ks[j][c * 8 + 4];
                fma2(a0, q2[c * 4 + 0], k01.x);
                fma2(a1, q2[c * 4 + 1], k01.y);
                fma2(a2, q2[c * 4 + 2], k23.x);
                fma2(a3, q2[c * 4 + 3], k23.y);
            }
            float2 f0 = upk2(a0), f1 = upk2(a1), f2 = upk2(a2), f3 = upk2(a3);
            float acc = ((f0.x + f0.y) + (f1.x + f1.y)) +
                        ((f2.x + f2.y) + (f3.x + f3.y));
            s[j] = (kstart + j <= qi) ? acc * 0.125f : -1e30f;
        }
        float mt = m;
#pragma unroll
        for (int j = 0; j < 32; j++) mt = fmaxf(mt, s[j]);
        float corr = __expf(m - mt);
        m = mt;
        l *= corr;
        ull c2 = pk2(corr);
#pragma unroll
        for (int d = 0; d < 32; d++) mul2(o2[d], c2);
#pragma unroll
        for (int j = 0; j < 32; j++) {
            float p = __expf(s[j] - m);
            l += p;
            ull p2 = pk2(p);
#pragma unroll
            for (int c = 0; c < 8; c++) {
                ulonglong2 v01 = *(const ulonglong2*)&Vs[j][c * 8];
                ulonglong2 v23 = *(const ulonglong2*)&Vs[j][c * 8 + 4];
                fma2(o2[c * 4 + 0], p2, v01.x);
                fma2(o2[c * 4 + 1], p2, v01.y);
                fma2(o2[c * 4 + 2], p2, v23.x);
                fma2(o2[c * 4 + 3], p2, v23.y);
            }
        }
    }
    float invl = 1.0f / l;
    float* op = Out + ((size_t)b * TSEQ + qi) * DMODEL + h * DHEAD;
#pragma unroll
    for (int d = 0; d < 32; d++) {
        float2 v = upk2(o2[d]);
        *(float2*)(op + d * 2) = make_float2(v.x * invl, v.y * invl);
    }
}

// ---------------------------------------------------------------------------
// Launch
// ---------------------------------------------------------------------------
extern "C" void kernel_launch(void* const* d_in, const int* in_sizes, int n_in,
                              void* d_out, int out_size) {
    const float* x     = (const float*)d_in[0];
    const int*   pos   = (const int*)d_in[1];
    const float* ln1   = (const float*)d_in[2];
    const float* ln2   = (const float*)d_in[3];
    const float* q_Us  = (const float*)d_in[4];
    const float* q_V   = (const float*)d_in[5];
    const float* k_Us  = (const float*)d_in[6];
    const float* k_V   = (const float*)d_in[7];
    const float* v_Us  = (const float*)d_in[8];
    const float* v_V   = (const float*)d_in[9];
    const float* o_Us  = (const float*)d_in[10];
    const float* o_V   = (const float*)d_in[11];
    const float* g_Us  = (const float*)d_in[12];
    const float* g_V   = (const float*)d_in[13];
    const float* u_Us  = (const float*)d_in[14];
    const float* u_V   = (const float*)d_in[15];
    const float* d_Us  = (const float*)d_in[16];
    const float* d_V   = (const float*)d_in[17];
    float* out = (float*)d_out;

    cudaFuncSetAttribute(mmfp16<0>, cudaFuncAttributeMaxDynamicSharedMemorySize, MM_SMEM);
    cudaFuncSetAttribute(mmfp16<1>, cudaFuncAttributeMaxDynamicSharedMemorySize, MM_SMEM);
    cudaFuncSetAttribute(mmfp16<2>, cudaFuncAttributeMaxDynamicSharedMemorySize, MM_SMEM);
    cudaFuncSetAttribute(mmfp16<3>, cudaFuncAttributeMaxDynamicSharedMemorySize, MM_SMEM);

    float* S = nullptr;
    cudaGetSymbolAddress((void**)&S, g_scratch);
    float* H  = S + OFF_H;
    float* Bb = S + OFF_B;
    float* C  = S + OFF_C;

    float* hbuf  = H;
    float* wc    = C;                        // 2304x2048
    float* qkvr  = Bb;                       // 2048x2304
    float* qb    = C;                        // 2*32*1024*64   (wc dead)
    float* kb    = C + 4194304;              // 2*8*1024*64
    float* vb    = C + 5242880;              // 2*8*1024*64
    float* attn  = H;                        // 2048x2048      (hbuf dead)
    float* ar    = Bb;                       // 2048x1024      (qkvr dead)
    float* wguv  = C;                        // 2048x2048      (qb/kb/vb dead)
    float* gu    = Bb;                       // 2048x2048      (ar dead)
    float* gate  = C;                        // 256x8192       (wguv dead after gu GEMM)
    float* inner = C + 2097152;              // 256x8192
    float* part  = C + 4194304;              // 8 x 256x1024
    float* dr    = H;                        // 2048x1024      (hbuf dead)

    // ---- attention sub-block ----
    rms_kernel<<<NTOK, 256>>>(x, ln1, hbuf);
    concat_qkv<<<4608, 256>>>(q_V, k_V, v_V, wc);
    mmfp16<0><<<dim3(18, 16), 256, MM_SMEM>>>(hbuf, wc, nullptr, qkvr, 2304, 2048, 2048, 2048);
    proj2_kernel<<<dim3(16, 48), 256>>>(qkvr, q_Us, k_Us, v_Us, pos, qb, kb, vb);
    flash_kernel<<<dim3(8, 64), 128>>>(qb, kb, vb, attn);
    mmfp16<0><<<dim3(8, 16), 256, MM_SMEM>>>(attn, o_V, nullptr, ar, 1024, 2048, 2048, 2048);
    mmfp16<1><<<dim3(16, 16), 256, MM_SMEM>>>(ar, o_Us, x, out, 2048, 1024, 1024, 1024);

    // ---- MLP sub-block ----
    rms_kernel<<<NTOK, 256>>>(out, ln2, hbuf);
    concat_guv<<<4096, 256>>>(g_V, u_V, wguv);
    mmfp16<0><<<dim3(16, 16), 256, MM_SMEM>>>(hbuf, wguv, nullptr, gu, 2048, 2048, 2048, 2048);

    for (int c = 0; c < NTOK / NCHUNK; c++) {
        const float* guc = gu + (size_t)c * NCHUNK * 2048;
        float* drc = dr + (size_t)c * NCHUNK * 1024;
        mmfp16<0><<<dim3(64, 2), 256, MM_SMEM>>>(guc, g_Us, nullptr, gate,
                                                 8192, 1024, 1024, 2048);
        mmfp16<3><<<dim3(64, 2), 256, MM_SMEM>>>(guc + 1024, u_Us, gate, inner,
                                                 8192, 1024, 1024, 2048);
        mmfp16<0><<<dim3(8, 2, 8), 256, MM_SMEM>>>(inner, d_V, nullptr, part,
                                                   1024, 8192, 1024, 8192);
        reduce8_kernel<<<256, 256>>>(part, drc);
    }
    mmfp16<2><<<dim3(16, 16), 256, MM_SMEM>>>(dr, d_Us, nullptr, out, 2048, 1024, 1024, 1024);
}

// round 17
// speedup vs baseline: 1.1829x; 1.1490x over previous
#include <cuda_runtime.h>
#include <cuda_fp16.h>
#include <cstdint>

// ---------------------------------------------------------------------------
// FlashSVDLlamaBlock R17: fp16 2-pass split GEMM (BK=64), MLP restructured
// over inter-dim slices (4 x [gate, up+silu, dV-accum]) — 23 graph nodes
// (was 42), no split-K partials, no reduce kernels.
//   B=2, T=1024, D=2048, H=32, HK=8, DH=64, R=48, RO=RFF=1024, INTER=8192
// Scratch (61 MB, phase-liveness reuse):
//   H [0..4,194,303]: hbuf -> attn -> hbuf -> gate_mc
//   B [4,194,304..8,912,895]: qkvr -> ar -> gu (live through MLP loop)
//   C [8,912,896..15,204,351]: wc -> qb/kb/vb -> wguv -> inner_mc + dr
// ---------------------------------------------------------------------------

#define NTOK 2048
#define DMODEL 2048
#define NH 32
#define NHK 8
#define DHEAD 64
#define RNK 48
#define TSEQ 1024

#define OFF_H 0u
#define OFF_B 4194304u
#define OFF_C 8912896u
#define SCRATCH_TOTAL 15204352u

__device__ float g_scratch[SCRATCH_TOTAL];

typedef unsigned long long ull;

// ---- packed f32x2 helpers (flash attention) --------------------------------
__device__ __forceinline__ ull pk2(float v) {
    ull r; asm("mov.b64 %0, {%1, %1};" : "=l"(r) : "f"(v)); return r;
}
__device__ __forceinline__ void fma2(ull& c, ull a, ull b) {
    asm("fma.rn.f32x2 %0, %1, %2, %0;" : "+l"(c) : "l"(a), "l"(b));
}
__device__ __forceinline__ void mul2(ull& c, ull a) {
    asm("mul.rn.f32x2 %0, %0, %1;" : "+l"(c) : "l"(a));
}
__device__ __forceinline__ float2 upk2(ull v) {
    float2 r; asm("mov.b64 {%0, %1}, %2;" : "=f"(r.x), "=f"(r.y) : "l"(v)); return r;
}

// ---- tensor-core helpers (base ISA, sm_80+) --------------------------------
__device__ __forceinline__ uint32_t smem_to_u32(const void* p) {
    uint32_t a;
    asm("{ .reg .u64 t; cvta.to.shared.u64 t, %1; cvt.u32.u64 %0, t; }"
        : "=r"(a) : "l"(p));
    return a;
}
__device__ __forceinline__ void ldmx4(uint32_t* r, uint32_t addr) {
    asm volatile("ldmatrix.sync.aligned.m8n8.x4.shared.b16 {%0,%1,%2,%3}, [%4];"
                 : "=r"(r[0]), "=r"(r[1]), "=r"(r[2]), "=r"(r[3]) : "r"(addr));
}
__device__ __forceinline__ void ldmx2(uint32_t* r, uint32_t addr) {
    asm volatile("ldmatrix.sync.aligned.m8n8.x2.shared.b16 {%0,%1}, [%2];"
                 : "=r"(r[0]), "=r"(r[1]) : "r"(addr));
}
__device__ __forceinline__ void mma_fp16(float* c, const uint32_t* a,
                                         const uint32_t* b) {
    asm volatile(
        "mma.sync.aligned.m16n8k16.row.col.f32.f16.f16.f32 "
        "{%0,%1,%2,%3}, {%4,%5,%6,%7}, {%8,%9}, {%0,%1,%2,%3};"
        : "+f"(c[0]), "+f"(c[1]), "+f"(c[2]), "+f"(c[3])
        : "r"(a[0]), "r"(a[1]), "r"(a[2]), "r"(a[3]), "r"(b[0]), "r"(b[1]));
}
__device__ __forceinline__ uint32_t h2pack(float x, float y) {
    __half2 h = __float22half2_rn(make_float2(x, y));
    return *(uint32_t*)&h;
}

// ---------------------------------------------------------------------------
// mmfp16: C[n,m] = sum_k A[n,k]*W[m,k], tensor cores, fp16 2-pass split:
//   C ≈ A_hi·W_hi + A_hi·W_lo
//   MODE 0: C = d;  1: C = d + RG[n,m];  2: C += d;  3: C = silu(RG[n,m]) * d
// Tile 128(tok) x 128(feat), 8 warps (2x4), warp tile 64x32, BK=64.
// One __syncthreads per 64-K chunk; loader split in K-halves.
// A row stride = lda; W row stride = ldw (column slicing of either operand).
// ---------------------------------------------------------------------------
#define ST_AHI 0
#define ST_WHI 18432
#define ST_WLO 36864
#define ST_STRIDE 55296
#define MM_SMEM 110592

template <int MODE>
__global__ void __launch_bounds__(256, 2) mmfp16(const float* __restrict__ A,
                                                 const float* __restrict__ W,
                                                 const float* __restrict__ RG,
                                                 float* __restrict__ C,
                                                 int M, int Kt, int lda, int ldw) {
    extern __shared__ __align__(16) char sm[];
    int tid = threadIdx.x;
    int wid = tid >> 5, lane = tid & 31;
    int m0 = blockIdx.x * 128, n0 = blockIdx.y * 128;
    const float* Ap = A + (size_t)n0 * lda;
    const float* Wp = W + (size_t)m0 * ldw;

    int wr = wid >> 2;          // warp row: 64 token-rows
    int wc = wid & 3;           // warp col: 32 feature-cols
    uint32_t sb = smem_to_u32(sm);

    // ldmatrix lane address offsets (bytes), row stride 144
    uint32_t aOff = (uint32_t)(wr * 64 + (lane & 7) + 8 * ((lane >> 3) & 1)) * 144
                  + ((lane >> 4) & 1) * 16;
    int lm = lane & 15;
    uint32_t bOff = (uint32_t)(wc * 32 + (lm & 7)) * 144 + ((lm >> 3) & 1) * 16;

    float c[4][4][4];
#pragma unroll
    for (int i = 0; i < 4; i++)
#pragma unroll
        for (int j = 0; j < 4; j++)
#pragma unroll
            for (int q = 0; q < 4; q++) c[i][j][q] = 0.f;

    int NC = Kt >> 6;

#define LDG_HALF(av, wv, kcol)                                                 \
    _Pragma("unroll")                                                          \
    for (int i = 0; i < 4; i++) {                                              \
        int s = tid + i * 256;                                                 \
        int row = s >> 3;                                                      \
        int c4 = (s & 7) * 4;                                                  \
        av[i] = *(const float4*)(Ap + (size_t)row * lda + (kcol) + c4);        \
        wv[i] = *(const float4*)(Wp + (size_t)row * ldw + (kcol) + c4);        \
    }

#define CVT_STS(stage_base, halfoff, av, wv)                                   \
    {                                                                          \
        char* stg = sm + (stage_base);                                         \
        _Pragma("unroll")                                                      \
        for (int i = 0; i < 4; i++) {                                          \
            int s = tid + i * 256;                                             \
            int row = s >> 3;                                                  \
            int c4 = (s & 7) * 4;                                              \
            uint32_t byte = (uint32_t)row * 144 + ((halfoff) + c4) * 2;        \
            float4 a = av[i], w = wv[i];                                       \
            *(uint2*)(stg + ST_AHI + byte) =                                   \
                make_uint2(h2pack(a.x, a.y), h2pack(a.z, a.w));                \
            uint32_t wh0 = h2pack(w.x, w.y), wh1 = h2pack(w.z, w.w);           \
            __half2 wf0 = *(__half2*)&wh0, wf1 = *(__half2*)&wh1;              \
            float2 f0 = __half22float2(wf0), f1 = __half22float2(wf1);         \
            *(uint2*)(stg + ST_WHI + byte) = make_uint2(wh0, wh1);             \
            *(uint2*)(stg + ST_WLO + byte) =                                   \
                make_uint2(h2pack(w.x - f0.x, w.y - f0.y),                     \
                           h2pack(w.z - f1.x, w.w - f1.y));                    \
        }                                                                      \
    }

#define MMA_K16(stg, k16)                                                      \
    {                                                                          \
        uint32_t kb = (k16) * 32;                                              \
        uint32_t ah[4][4];                                                     \
        _Pragma("unroll")                                                      \
        for (int mi = 0; mi < 4; mi++)                                         \
            ldmx4(ah[mi], sb + (stg) + ST_AHI + aOff + mi * 2304 + kb);        \
        _Pragma("unroll")                                                      \
        for (int ni = 0; ni < 4; ni++) {                                       \
            uint32_t bh[2], bl[2];                                             \
            ldmx2(bh, sb + (stg) + ST_WHI + bOff + ni * 1152 + kb);            \
            ldmx2(bl, sb + (stg) + ST_WLO + bOff + ni * 1152 + kb);            \
            _Pragma("unroll")                                                  \
            for (int mi = 0; mi < 4; mi++) {                                   \
                mma_fp16(c[mi][ni], ah[mi], bh);                               \
                mma_fp16(c[mi][ni], ah[mi], bl);                               \
            }                                                                  \
        }                                                                      \
    }

    // prologue: fill stage 0 (both halves)
    {
        float4 av[4], wv[4];
        LDG_HALF(av, wv, 0);
        CVT_STS(0, 0, av, wv);
        LDG_HALF(av, wv, 32);
        CVT_STS(0, 32, av, wv);
    }
    __syncthreads();

    for (int ch = 0; ch < NC; ch++) {
        int cur = ch & 1;
        bool has = (ch + 1 < NC);
        uint32_t stg = (uint32_t)(cur * ST_STRIDE);
        uint32_t nxt = (uint32_t)((cur ^ 1) * ST_STRIDE);
        float4 av[4], wv[4];
        if (has) LDG_HALF(av, wv, (ch + 1) * 64);
        MMA_K16(stg, 0);
        MMA_K16(stg, 1);
        if (has) {
            CVT_STS(nxt, 0, av, wv);
            LDG_HALF(av, wv, (ch + 1) * 64 + 32);
        }
        MMA_K16(stg, 2);
        MMA_K16(stg, 3);
        if (has) CVT_STS(nxt, 32, av, wv);
        __syncthreads();
    }
#undef LDG_HALF
#undef CVT_STS
#undef MMA_K16

    // epilogue: D fragment c0..c3 -> rows (g, g+8), cols (2t, 2t+1)
    int g = lane >> 2, t = lane & 3;
#pragma unroll
    for (int mi = 0; mi < 4; mi++) {
#pragma unroll
        for (int ni = 0; ni < 4; ni++) {
            int row0 = n0 + wr * 64 + mi * 16 + g;
            int col = m0 + wc * 32 + ni * 8 + t * 2;
            size_t i0 = (size_t)row0 * M + col;
            size_t i1 = i0 + (size_t)8 * M;
            float2 v0 = make_float2(c[mi][ni][0], c[mi][ni][1]);
            float2 v1 = make_float2(c[mi][ni][2], c[mi][ni][3]);
            if (MODE == 1) {
                float2 r0 = *(const float2*)&RG[i0];
                float2 r1 = *(const float2*)&RG[i1];
                v0.x += r0.x; v0.y += r0.y; v1.x += r1.x; v1.y += r1.y;
            }
            if (MODE == 2) {
                float2 r0 = *(const float2*)&C[i0];
                float2 r1 = *(const float2*)&C[i1];
                v0.x += r0.x; v0.y += r0.y; v1.x += r1.x; v1.y += r1.y;
            }
            if (MODE == 3) {
                float2 g0 = *(const float2*)&RG[i0];
                float2 g1 = *(const float2*)&RG[i1];
                v0.x *= g0.x / (1.0f + __expf(-g0.x));
                v0.y *= g0.y / (1.0f + __expf(-g0.y));
                v1.x *= g1.x / (1.0f + __expf(-g1.x));
                v1.y *= g1.y / (1.0f + __expf(-g1.y));
            }
            *(float2*)&C[i0] = v0;
            *(float2*)&C[i1] = v1;
        }
    }
}

// ---------------------------------------------------------------------------
// RMSNorm
// ---------------------------------------------------------------------------
__global__ void __launch_bounds__(256) rms_kernel(const float* __restrict__ x,
                                                  const float* __restrict__ w,
                                                  float* __restrict__ out) {
    int n = blockIdx.x;
    int tid = threadIdx.x;
    const float4* xr = (const float4*)(x + (size_t)n * DMODEL);
    float4 loc[2];
    float ss = 0.f;
#pragma unroll
    for (int i = 0; i < 2; i++) {
        float4 v = xr[tid + i * 256];
        loc[i] = v;
        ss += v.x * v.x + v.y * v.y + v.z * v.z + v.w * v.w;
    }
#pragma unroll
    for (int off = 16; off; off >>= 1)
        ss += __shfl_xor_sync(0xffffffffu, ss, off);
    __shared__ float red[8];
    if ((tid & 31) == 0) red[tid >> 5] = ss;
    __syncthreads();
    float tot = red[0] + red[1] + red[2] + red[3] + red[4] + red[5] + red[6] + red[7];
    float inv = rsqrtf(tot * (1.0f / (float)DMODEL) + 1e-5f);
    const float4* w4 = (const float4*)w;
    float4* o4 = (float4*)(out + (size_t)n * DMODEL);
#pragma unroll
    for (int i = 0; i < 2; i++) {
        int idx = tid + i * 256;
        float4 wv = w4[idx];
        float4 v = loc[i];
        o4[idx] = make_float4(v.x * inv * wv.x, v.y * inv * wv.y,
                              v.z * inv * wv.z, v.w * inv * wv.w);
    }
}

// ---------------------------------------------------------------------------
// qkv weight concat: wc = [q_V(1536x2048); k_V(384x2048); v_V(384x2048)]
// ---------------------------------------------------------------------------
__global__ void __launch_bounds__(256) concat_qkv(const float* __restrict__ q,
                                                  const float* __restrict__ k,
                                                  const float* __restrict__ v,
                                                  float* __restrict__ wc) {
    int i = blockIdx.x * 256 + threadIdx.x;
    float4 val;
    if (i < 786432) val = ((const float4*)q)[i];
    else if (i < 983040) val = ((const float4*)k)[i - 786432];
    else val = ((const float4*)v)[i - 983040];
    ((float4*)wc)[i] = val;
}

// ---------------------------------------------------------------------------
// gate/up weight concat: wguv = [g_V(1024x2048); u_V(1024x2048)]
// ---------------------------------------------------------------------------
__global__ void __launch_bounds__(256) concat_guv(const float* __restrict__ gw,
                                                  const float* __restrict__ uw,
                                                  float* __restrict__ wguv) {
    int i = blockIdx.x * 256 + threadIdx.x;     // float4 index, total 1,048,576
    float4 val = (i < 524288) ? ((const float4*)gw)[i]
                              : ((const float4*)uw)[i - 524288];
    ((float4*)wguv)[i] = val;
}

// ---------------------------------------------------------------------------
// Batched per-head Us projection + fused RoPE (R6 version).
// ---------------------------------------------------------------------------
__global__ void __launch_bounds__(256) proj2_kernel(
    const float* __restrict__ Rv,
    const float* __restrict__ q_Us, const float* __restrict__ k_Us,
    const float* __restrict__ v_Us,
    const int* __restrict__ pos_ids,
    float* __restrict__ qb, float* __restrict__ kb, float* __restrict__ vb) {
    int hidx = blockIdx.y;
    int n0 = blockIdx.x * 128;
    int tid = threadIdx.x;
    __shared__ float Rvs[48][128];
    __shared__ float Uss[48][64];

#pragma unroll
    for (int i = 0; i < 6; i++) {
        int f = tid + i * 256;
        int r = f / 12, c4 = (f % 12) * 4;
        float4 v = *(const float4*)&Rv[(size_t)(n0 + r) * 2304 + hidx * 48 + c4];
        Rvs[c4 + 0][r] = v.x; Rvs[c4 + 1][r] = v.y;
        Rvs[c4 + 2][r] = v.z; Rvs[c4 + 3][r] = v.w;
    }
    const float* Us = (hidx < 32) ? q_Us + (size_t)hidx * 3072
                    : (hidx < 40) ? k_Us + (size_t)(hidx - 32) * 3072
                                  : v_Us + (size_t)(hidx - 40) * 3072;
#pragma unroll
    for (int i = 0; i < 3; i++) {
        int f = tid + i * 256;
        int dh = f / 12, c4 = (f % 12) * 4;
        float4 v = *(const float4*)&Us[dh * 48 + c4];
        Uss[c4 + 0][dh] = v.x; Uss[c4 + 1][dh] = v.y;
        Uss[c4 + 2][dh] = v.z; Uss[c4 + 3][dh] = v.w;
    }
    __syncthreads();

    int tx = tid & 7;
    int ty = tid >> 3;
    float acc[4][8];
#pragma unroll
    for (int i = 0; i < 4; i++)
#pragma unroll
        for (int j = 0; j < 8; j++) acc[i][j] = 0.f;

#pragma unroll 8
    for (int k = 0; k < 48; k++) {
        float4 a = *(const float4*)&Rvs[k][ty * 4];
        float4 w0 = *(const float4*)&Uss[k][tx * 8];
        float4 w1 = *(const float4*)&Uss[k][tx * 8 + 4];
        float av[4] = {a.x, a.y, a.z, a.w};
        float wv[8] = {w0.x, w0.y, w0.z, w0.w, w1.x, w1.y, w1.z, w1.w};
#pragma unroll
        for (int i = 0; i < 4; i++)
#pragma unroll
            for (int j = 0; j < 8; j++) acc[i][j] += av[i] * wv[j];
    }

    float prt[4][8];
#pragma unroll
    for (int i = 0; i < 4; i++)
#pragma unroll
        for (int j = 0; j < 8; j++)
            prt[i][j] = __shfl_xor_sync(0xffffffffu, acc[i][j], 4);

    bool dorope = (hidx < 40);
    float sgn = (tx < 4) ? -1.f : 1.f;
    float invf[4];
    if (dorope) {
#pragma unroll
        for (int fj = 0; fj < 4; fj++)
            invf[fj] = expf(-(float)(tx * 4 + fj) * (9.210340371976184f / 32.0f));
    }

    float* outp;
    int hh, nh;
    if (hidx < 32)      { outp = qb; hh = hidx;      nh = NH;  }
    else if (hidx < 40) { outp = kb; hh = hidx - 32; nh = NHK; }
    else                { outp = vb; hh = hidx - 40; nh = NHK; }

#pragma unroll
    for (int i = 0; i < 4; i++) {
        int n = n0 + ty * 4 + i;
        int b = n >> 10;
        int t = n & 1023;
        float vals[8];
        if (dorope) {
            float pos = (float)pos_ids[t];
#pragma unroll
            for (int fj = 0; fj < 4; fj++) {
                float ang = pos * invf[fj];
                float c = cosf(ang), s = sinf(ang);
                vals[fj * 2 + 0] = acc[i][fj * 2 + 0] * c + sgn * prt[i][fj * 2 + 0] * s;
                vals[fj * 2 + 1] = acc[i][fj * 2 + 1] * c + sgn * prt[i][fj * 2 + 1] * s;
            }
        } else {
#pragma unroll
            for (int j = 0; j < 8; j++) vals[j] = acc[i][j];
        }
        float* op = outp + (((size_t)b * nh + hh) * TSEQ + t) * DHEAD + tx * 8;
        *(float4*)op       = make_float4(vals[0], vals[1], vals[2], vals[3]);
        *(float4*)(op + 4) = make_float4(vals[4], vals[5], vals[6], vals[7]);
    }
}

// ---------------------------------------------------------------------------
// Causal flash attention, packed f32x2 + __expf (R6 version).
// ---------------------------------------------------------------------------
__global__ void __launch_bounds__(128) flash_kernel(const float* __restrict__ Q,
                                                    const float* __restrict__ Kg,
                                                    const float* __restrict__ Vg,
                                                    float* __restrict__ Out) {
    int bh = blockIdx.y;
    int b = bh >> 5;
    int h = bh & 31;
    int hk = h >> 2;
    int q0 = blockIdx.x * 128;
    int tid = threadIdx.x;
    int qi = q0 + tid;

    __shared__ __align__(16) float Ks[32][64];
    __shared__ __align__(16) float Vs[32][64];

    ull q2[32];
    const float* qp = Q + (((size_t)b * NH + h) * TSEQ + qi) * DHEAD;
#pragma unroll
    for (int c = 0; c < 16; c++) {
        ulonglong2 t = *(const ulonglong2*)(qp + c * 4);
        q2[c * 2] = t.x; q2[c * 2 + 1] = t.y;
    }
    float m = -1e30f, l = 0.f;
    ull o2[32];
#pragma unroll
    for (int d = 0; d < 32; d++) o2[d] = 0ull;

    const float* kbase = Kg + (((size_t)b * NHK + hk) * TSEQ) * DHEAD;
    const float* vbase = Vg + (((size_t)b * NHK + hk) * TSEQ) * DHEAD;
    int nkt = (q0 + 128) / 32;

    for (int kt = 0; kt < nkt; kt++) {
        int kstart = kt * 32;
        __syncthreads();
#pragma unroll
        for (int i = 0; i < 4; i++) {
            int e = tid + i * 128;
            int row = e >> 4;
            int col = (e & 15) * 4;
            *(float4*)&Ks[row][col] = *(const float4*)(kbase + (size_t)(kstart + row) * 64 + col);
            *(float4*)&Vs[row][col] = *(const float4*)(vbase + (size_t)(kstart + row) * 64 + col);
        }
        __syncthreads();

        float s[32];
#pragma unroll
        for (int j = 0; j < 32; j++) {
            ull a0 = 0ull, a1 = 0ull, a2 = 0ull, a3 = 0ull;
#pragma unroll
            for (int c = 0; c < 8; c++) {
                ulonglong2 k01 = *(const ulonglong2*)&Ks[j][c * 8];
                ulonglong2 k23 = *(const ulonglong2*)&Ks[j][c * 8 + 4];
                fma2(a0, q2[c * 4 + 0], k01.x);
                fma2(a1, q2[c * 4 + 1], k01.y);
                fma2(a2, q2[c * 4 + 2], k23.x);
                fma2(a3, q2[c * 4 + 3], k23.y);
            }
            float2 f0 = upk2(a0), f1 = upk2(a1), f2 = upk2(a2), f3 = upk2(a3);
            float acc = ((f0.x + f0.y) + (f1.x + f1.y)) +
                        ((f2.x + f2.y) + (f3.x + f3.y));
            s[j] = (kstart + j <= qi) ? acc * 0.125f : -1e30f;
        }
        float mt = m;
#pragma unroll
        for (int j = 0; j < 32; j++) mt = fmaxf(mt, s[j]);
        float corr = __expf(m - mt);
        m = mt;
        l *= corr;
        ull c2 = pk2(corr);
#pragma unroll
        for (int d = 0; d < 32; d++) mul2(o2[d], c2);
#pragma unroll
        for (int j = 0; j < 32; j++) {
            float p = __expf(s[j] - m);
            l += p;
            ull p2 = pk2(p);
#pragma unroll
            for (int c = 0; c < 8; c++) {
                ulonglong2 v01 = *(const ulonglong2*)&Vs[j][c * 8];
                ulonglong2 v23 = *(const ulonglong2*)&Vs[j][c * 8 + 4];
                fma2(o2[c * 4 + 0], p2, v01.x);
                fma2(o2[c * 4 + 1], p2, v01.y);
                fma2(o2[c * 4 + 2], p2, v23.x);
                fma2(o2[c * 4 + 3], p2, v23.y);
            }
        }
    }
    float invl = 1.0f / l;
    float* op = Out + ((size_t)b * TSEQ + qi) * DMODEL + h * DHEAD;
#pragma unroll
    for (int d = 0; d < 32; d++) {
        float2 v = upk2(o2[d]);
        *(float2*)(op + d * 2) = make_float2(v.x * invl, v.y * invl);
    }
}

// ---------------------------------------------------------------------------
// Launch — 23 graph nodes total
// ---------------------------------------------------------------------------
extern "C" void kernel_launch(void* const* d_in, const int* in_sizes, int n_in,
                              void* d_out, int out_size) {
    const float* x     = (const float*)d_in[0];
    const int*   pos   = (const int*)d_in[1];
    const float* ln1   = (const float*)d_in[2];
    const float* ln2   = (const float*)d_in[3];
    const float* q_Us  = (const float*)d_in[4];
    const float* q_V   = (const float*)d_in[5];
    const float* k_Us  = (const float*)d_in[6];
    const float* k_V   = (const float*)d_in[7];
    const float* v_Us  = (const float*)d_in[8];
    const float* v_V   = (const float*)d_in[9];
    const float* o_Us  = (const float*)d_in[10];
    const float* o_V   = (const float*)d_in[11];
    const float* g_Us  = (const float*)d_in[12];
    const float* g_V   = (const float*)d_in[13];
    const float* u_Us  = (const float*)d_in[14];
    const float* u_V   = (const float*)d_in[15];
    const float* d_Us  = (const float*)d_in[16];
    const float* d_V   = (const float*)d_in[17];
    float* out = (float*)d_out;

    cudaFuncSetAttribute(mmfp16<0>, cudaFuncAttributeMaxDynamicSharedMemorySize, MM_SMEM);
    cudaFuncSetAttribute(mmfp16<1>, cudaFuncAttributeMaxDynamicSharedMemorySize, MM_SMEM);
    cudaFuncSetAttribute(mmfp16<2>, cudaFuncAttributeMaxDynamicSharedMemorySize, MM_SMEM);
    cudaFuncSetAttribute(mmfp16<3>, cudaFuncAttributeMaxDynamicSharedMemorySize, MM_SMEM);

    float* S = nullptr;
    cudaGetSymbolAddress((void**)&S, g_scratch);
    float* H  = S + OFF_H;
    float* Bb = S + OFF_B;
    float* C  = S + OFF_C;

    float* hbuf  = H;
    float* wc    = C;                        // 2304x2048
    float* qkvr  = Bb;                       // 2048x2304
    float* qb    = C;                        // 2*32*1024*64   (wc dead)
    float* kb    = C + 4194304;              // 2*8*1024*64
    float* vb    = C + 5242880;              // 2*8*1024*64
    float* attn  = H;                        // 2048x2048      (hbuf dead)
    float* ar    = Bb;                       // 2048x1024      (qkvr dead)
    float* wguv  = C;                        // 2048x2048      (qb/kb/vb dead)
    float* gu    = Bb;                       // 2048x2048      (ar dead; live all loop)
    float* gatem = H;                        // 2048x2048      (hbuf dead after gu)
    float* innm  = C;                        // 2048x2048      (wguv dead)
    float* dr    = C + 4194304;              // 2048x1024

    // ---- attention sub-block ----
    rms_kernel<<<NTOK, 256>>>(x, ln1, hbuf);
    concat_qkv<<<4608, 256>>>(q_V, k_V, v_V, wc);
    mmfp16<0><<<dim3(18, 16), 256, MM_SMEM>>>(hbuf, wc, nullptr, qkvr,
                                              2304, 2048, 2048, 2048);
    proj2_kernel<<<dim3(16, 48), 256>>>(qkvr, q_Us, k_Us, v_Us, pos, qb, kb, vb);
    flash_kernel<<<dim3(8, 64), 128>>>(qb, kb, vb, attn);
    mmfp16<0><<<dim3(8, 16), 256, MM_SMEM>>>(attn, o_V, nullptr, ar,
                                             1024, 2048, 2048, 2048);
    mmfp16<1><<<dim3(16, 16), 256, MM_SMEM>>>(ar, o_Us, x, out,
                                              2048, 1024, 1024, 1024);

    // ---- MLP sub-block ----
    rms_kernel<<<NTOK, 256>>>(out, ln2, hbuf);
    concat_guv<<<4096, 256>>>(g_V, u_V, wguv);
    mmfp16<0><<<dim3(16, 16), 256, MM_SMEM>>>(hbuf, wguv, nullptr, gu,
                                              2048, 2048, 2048, 2048);

    // inter-dim slices of 2048: gate -> up+silu -> dV accumulate
    for (int mc = 0; mc < 4; mc++) {
        const float* gUsm = g_Us + (size_t)mc * 2048 * 1024;
        const float* uUsm = u_Us + (size_t)mc * 2048 * 1024;
        const float* dVm  = d_V + (size_t)mc * 2048;
        mmfp16<0><<<dim3(16, 16), 256, MM_SMEM>>>(gu, gUsm, nullptr, gatem,
                                                  2048, 1024, 2048, 1024);
        mmfp16<3><<<dim3(16, 16), 256, MM_SMEM>>>(gu + 1024, uUsm, gatem, innm,
                                                  2048, 1024, 2048, 1024);
        if (mc == 0)
            mmfp16<0><<<dim3(8, 16), 256, MM_SMEM>>>(innm, dVm, nullptr, dr,
                                                     1024, 2048, 2048, 8192);
        else
            mmfp16<2><<<dim3(8, 16), 256, MM_SMEM>>>(innm, dVm, nullptr, dr,
                                                     1024, 2048, 2048, 8192);
    }
    mmfp16<2><<<dim3(16, 16), 256, MM_SMEM>>>(dr, d_Us, nullptr, out,
                                              2048, 1024, 1024, 1024);
}